// round 4
// baseline (speedup 1.0000x reference)
#include <cuda_runtime.h>

#define BATCH 512
#define INF   512
#define OUTF  100
#define KD    5
#define OKC   500            // OUTF * KD
#define PLANE (OKC * BATCH)  // 256000
#define NZ    8              // split-K factor
#define LOG2E 1.4426950408889634f

typedef unsigned long long u64;

// Split-K partial GEMM results, [z][c][b] with c = o*KD + k, pre-scaled by log2e.
__device__ float g_Mp[NZ][PLANE];

// Triangular tile map (jb, ib) with ib <= jb, 4x4 -> 10 tiles.
__constant__ int c_jb[10] = {0,1,1,2,2,2,3,3,3,3};
__constant__ int c_ib[10] = {0,0,1,0,1,2,0,1,2,3};

// ---- packed f32x2 helpers ----
__device__ __forceinline__ u64 f2add(u64 a, u64 b) {
    u64 r; asm("add.rn.f32x2 %0,%1,%2;" : "=l"(r) : "l"(a), "l"(b)); return r;
}
__device__ __forceinline__ u64 f2fma(u64 a, u64 b, u64 c) {
    u64 r; asm("fma.rn.f32x2 %0,%1,%2,%3;" : "=l"(r) : "l"(a), "l"(b), "l"(c)); return r;
}
__device__ __forceinline__ u64 pk(float lo, float hi) {
    u64 r; asm("mov.b64 %0,{%1,%2};" : "=l"(r) : "f"(lo), "f"(hi)); return r;
}
__device__ __forceinline__ void upk(u64 a, float& lo, float& hi) {
    asm("mov.b64 {%0,%1},%2;" : "=f"(lo), "=f"(hi) : "l"(a));
}
__device__ __forceinline__ float ex2_approx(float x) {
    float y; asm("ex2.approx.ftz.f32 %0, %1;" : "=f"(y) : "f"(x)); return y;
}
#define NEGABS_MASK 0x8000000080000000ULL   // OR -> -(|x|) on both halves

// ---------------------------------------------------------------------------
// Kernel 1: split-K GEMM, FFMA2 with m-packed accumulators.
// g_Mp[z][c][b] = LOG2E * sum_{k in slice z} X[b][k] * W[k][c]
// Block tile 128m x 128n, 256 threads, 8m x 8n per thread, BK=16, K-slice 64.
// A transposed in smem (As[kk][m]) -> natural m-pairs; B duplicated in regs.
// grid = (4 n, 4 m, 8 z) = 128 blocks.
// ---------------------------------------------------------------------------
__global__ void __launch_bounds__(256)
gemm_kernel(const float* __restrict__ X, const float* __restrict__ W) {
    __shared__ __align__(16) float As[2][16][128];   // 8 KB x2
    __shared__ __align__(16) float Bs[2][16][128];   // 8 KB x2

    const int tid = threadIdx.x;
    const int tx  = tid & 15;            // n octet
    const int ty  = tid >> 4;            // m octet
    const int m0  = blockIdx.y * 128;
    const int n0  = blockIdx.x * 128;
    const int k0  = blockIdx.z * 64;

    // A loader: row amr (0..127), k-half akh (0 or 8). Stores transposed.
    const int amr = tid & 127;
    const int akh = (tid >> 7) * 8;
    const float* xp = X + (m0 + amr) * INF + k0 + akh;

    // B loader: row bkr (0..15), quads bc0 and bc0+64 (coalesced, direct).
    const int bkr = tid >> 4;
    const int bc0 = n0 + (tid & 15) * 4;
    const int bc1 = bc0 + 64;
    const bool ok0 = bc0 < OKC;
    const bool ok1 = bc1 < OKC;
    const float4 fz = make_float4(0.f, 0.f, 0.f, 0.f);

    // prologue: tile 0 -> buf 0
    float4 av0 = *(const float4*)(xp);
    float4 av1 = *(const float4*)(xp + 4);
    const float* wr = W + (k0 + bkr) * OKC;
    float4 bv0 = ok0 ? *(const float4*)(wr + bc0) : fz;
    float4 bv1 = ok1 ? *(const float4*)(wr + bc1) : fz;
    As[0][akh + 0][amr] = av0.x;  As[0][akh + 1][amr] = av0.y;
    As[0][akh + 2][amr] = av0.z;  As[0][akh + 3][amr] = av0.w;
    As[0][akh + 4][amr] = av1.x;  As[0][akh + 5][amr] = av1.y;
    As[0][akh + 6][amr] = av1.z;  As[0][akh + 7][amr] = av1.w;
    *(float4*)&Bs[0][bkr][(tid & 15) * 4]      = bv0;
    *(float4*)&Bs[0][bkr][(tid & 15) * 4 + 64] = bv1;
    __syncthreads();

    u64 acc[8][4];
    #pragma unroll
    for (int n = 0; n < 8; n++)
        #pragma unroll
        for (int p = 0; p < 4; p++) acc[n][p] = 0ULL;

    for (int kt = 0; kt < 4; kt++) {
        const int cur = kt & 1;
        if (kt < 3) {
            av0 = *(const float4*)(xp + (kt + 1) * 16);
            av1 = *(const float4*)(xp + (kt + 1) * 16 + 4);
            const float* wn = W + (k0 + (kt + 1) * 16 + bkr) * OKC;
            bv0 = ok0 ? *(const float4*)(wn + bc0) : fz;
            bv1 = ok1 ? *(const float4*)(wn + bc1) : fz;
        }
        #pragma unroll
        for (int kk = 0; kk < 16; kk++) {
            float4 a0 = *(const float4*)&As[cur][kk][ty * 8];
            float4 a1 = *(const float4*)&As[cur][kk][ty * 8 + 4];
            float4 b0 = *(const float4*)&Bs[cur][kk][tx * 8];
            float4 b1 = *(const float4*)&Bs[cur][kk][tx * 8 + 4];
            u64 ap0 = pk(a0.x, a0.y), ap1 = pk(a0.z, a0.w);
            u64 ap2 = pk(a1.x, a1.y), ap3 = pk(a1.z, a1.w);
            u64 bd[8];
            bd[0] = pk(b0.x, b0.x); bd[1] = pk(b0.y, b0.y);
            bd[2] = pk(b0.z, b0.z); bd[3] = pk(b0.w, b0.w);
            bd[4] = pk(b1.x, b1.x); bd[5] = pk(b1.y, b1.y);
            bd[6] = pk(b1.z, b1.z); bd[7] = pk(b1.w, b1.w);
            #pragma unroll
            for (int n = 0; n < 8; n++) {
                acc[n][0] = f2fma(ap0, bd[n], acc[n][0]);
                acc[n][1] = f2fma(ap1, bd[n], acc[n][1]);
                acc[n][2] = f2fma(ap2, bd[n], acc[n][2]);
                acc[n][3] = f2fma(ap3, bd[n], acc[n][3]);
            }
        }
        if (kt < 3) {
            const int nxt = cur ^ 1;
            As[nxt][akh + 0][amr] = av0.x;  As[nxt][akh + 1][amr] = av0.y;
            As[nxt][akh + 2][amr] = av0.z;  As[nxt][akh + 3][amr] = av0.w;
            As[nxt][akh + 4][amr] = av1.x;  As[nxt][akh + 5][amr] = av1.y;
            As[nxt][akh + 6][amr] = av1.z;  As[nxt][akh + 7][amr] = av1.w;
            *(float4*)&Bs[nxt][bkr][(tid & 15) * 4]      = bv0;
            *(float4*)&Bs[nxt][bkr][(tid & 15) * 4 + 64] = bv1;
            __syncthreads();
        }
    }

    // epilogue: store column-major [c][b], scaled by log2e. m-pairs contiguous.
    float* plane = g_Mp[blockIdx.z];
    #pragma unroll
    for (int n = 0; n < 8; n++) {
        int c = n0 + tx * 8 + n;
        if (c < OKC) {
            float v[8];
            upk(acc[n][0], v[0], v[1]); upk(acc[n][1], v[2], v[3]);
            upk(acc[n][2], v[4], v[5]); upk(acc[n][3], v[6], v[7]);
            float4 o0 = make_float4(v[0] * LOG2E, v[1] * LOG2E, v[2] * LOG2E, v[3] * LOG2E);
            float4 o1 = make_float4(v[4] * LOG2E, v[5] * LOG2E, v[6] * LOG2E, v[7] * LOG2E);
            *(float4*)&plane[c * BATCH + m0 + ty * 8]     = o0;
            *(float4*)&plane[c * BATCH + m0 + ty * 8 + 4] = o1;
        }
    }
}

// ---------------------------------------------------------------------------
// Kernel 2: symmetric pairwise. Square 128x128 (j,i) tiles, only ib <= jb.
// Off-diag tiles add row sums to out[j] and (by symmetry) col sums to out[i].
// i-index skewed per lane so col sums use conflict-free per-warp smem RMW.
// grid = (100 o, 10 tiles), 128 threads.
// ---------------------------------------------------------------------------
template <bool COL>
__device__ __forceinline__ u64 tile_loop(const float (*sI)[128], unsigned cs_addr,
                                         const u64* nm, int lane) {
    u64 acc = 0ULL;
    #pragma unroll 4
    for (int s = 0; s < 64; s++) {
        int q = (s + lane) & 63;
        u64 p0 = *(const u64*)&sI[0][2 * q];
        u64 p1 = *(const u64*)&sI[1][2 * q];
        u64 p2 = *(const u64*)&sI[2][2 * q];
        u64 p3 = *(const u64*)&sI[3][2 * q];
        u64 p4 = *(const u64*)&sI[4][2 * q];
        u64 n0 = f2add(p0, nm[0]) | NEGABS_MASK;   // -(|Mi - Mj|), both halves
        u64 n1 = f2add(p1, nm[1]) | NEGABS_MASK;
        u64 n2 = f2add(p2, nm[2]) | NEGABS_MASK;
        u64 n3 = f2add(p3, nm[3]) | NEGABS_MASK;
        u64 n4 = f2add(p4, nm[4]) | NEGABS_MASK;
        u64 sm = f2add(f2add(n0, n1), f2add(n2, n3));
        sm = f2add(sm, n4);                        // (-norm_lo, -norm_hi)
        float s0, s1; upk(sm, s0, s1);
        u64 e = pk(ex2_approx(s0), ex2_approx(s1));
        acc = f2add(acc, e);
        if (COL) {
            unsigned a = cs_addr + q * 8;
            u64 cv;
            asm volatile("ld.volatile.shared.b64 %0, [%1];" : "=l"(cv) : "r"(a));
            cv = f2add(cv, e);
            asm volatile("st.volatile.shared.b64 [%0], %1;" :: "r"(a), "l"(cv));
        }
    }
    return acc;
}

__global__ void __launch_bounds__(128)
pairwise_kernel(float* __restrict__ out) {
    const int o   = blockIdx.x;
    const int t   = blockIdx.y;
    const int jb  = c_jb[t], ib = c_ib[t];
    const bool offdiag = (jb != ib);
    const int tid = threadIdx.x;
    const int lane = tid & 31, w = tid >> 5;
    const int j   = jb * 128 + tid;
    const int i0  = ib * 128;

    __shared__ __align__(16) float sI[KD][128];     // 2.5 KB i-slice (SoA)
    __shared__ __align__(16) float csum[4][128];    // 2 KB per-warp col sums

    // stage i-slice, summing the NZ split-K planes (coalesced).
    #pragma unroll
    for (int idx = tid; idx < KD * 128; idx += 128) {
        int k = idx >> 7, b = idx & 127;
        const float* p = g_Mp[0] + (o * KD + k) * BATCH + i0 + b;
        float s = 0.f;
        #pragma unroll
        for (int z = 0; z < NZ; z++) s += p[z * PLANE];
        sI[k][b] = s;
    }
    #pragma unroll
    for (int q = 0; q < 4; q++) csum[q][tid] = 0.f;

    // own j-row, negated & duplicated into packed regs.
    u64 nm[KD];
    #pragma unroll
    for (int k = 0; k < KD; k++) {
        const float* p = g_Mp[0] + (o * KD + k) * BATCH + j;
        float m = 0.f;
        #pragma unroll
        for (int z = 0; z < NZ; z++) m += p[z * PLANE];
        nm[k] = pk(-m, -m);
    }
    __syncthreads();

    unsigned cs_addr = (unsigned)__cvta_generic_to_shared(&csum[w][0]);

    u64 acc = offdiag ? tile_loop<true>(sI, cs_addr, nm, lane)
                      : tile_loop<false>(sI, cs_addr, nm, lane);

    float alo, ahi; upk(acc, alo, ahi);
    float r = alo + ahi - (offdiag ? 0.f : 1.0f);   // diag: remove self exp2(0)
    atomicAdd(&out[j * OUTF + o], r);

    if (offdiag) {
        __syncthreads();
        float c = csum[0][tid] + csum[1][tid] + csum[2][tid] + csum[3][tid];
        atomicAdd(&out[(i0 + tid) * OUTF + o], c);
    }
}

// ---------------------------------------------------------------------------
extern "C" void kernel_launch(void* const* d_in, const int* in_sizes, int n_in,
                              void* d_out, int out_size) {
    const float* x = (const float*)d_in[0];   // [512, 512]
    const float* T = (const float*)d_in[1];   // [512, 100, 5] == [512, 500]
    float* out = (float*)d_out;               // [512, 100]

    cudaMemsetAsync(out, 0, BATCH * OUTF * sizeof(float));

    dim3 ggrid(4, 4, NZ);                     // 128 blocks
    gemm_kernel<<<ggrid, 256>>>(x, T);

    dim3 pgrid(OUTF, 10);                     // 1000 blocks
    pairwise_kernel<<<pgrid, 128>>>(out);
}